// round 14
// baseline (speedup 1.0000x reference)
#include <cuda_runtime.h>
#include <cuda_bf16.h>
#include <cstdint>
#include <math.h>

#define NA 1000
#define KP 100000
#define BD 256
#define NAB (NA + BD)        // 1256 stacked rows (pub ; priv)
#define MT 10                // row tiles in merged GEMM (1280 rows padded)
#define NTRI 7               // row tiles 0..6 are pure-S triangular (2-pass)
#define ZS 6                 // split-K slices for merged GEMM
#define KPAD 1024
#define RICH_ITERS 11
#define POW_ITERS 6
#define NCTA_SOLVE 16

// Tile: CTA 128x128, BK=32, 8 warps (4m x 2n), warp tile 32x64.
// Smem tile: 128 rows x 40 halves (32 data + 8 pad) = 10240 B; 4 tiles/stage.
#define TILE_B  10240
#define STAGE_B (4 * TILE_B)   // 40960

// ---------------- device scratch ----------------
__device__ __align__(16) __nv_bfloat16 g_allH[(size_t)NAB * KP];   // [pub;priv] hi
__device__ __align__(16) __nv_bfloat16 g_allL[(size_t)NAB * KP];   // [pub;priv] lo
__device__ __align__(16) __nv_bfloat16 g_pubTH[(size_t)KP * KPAD];
__device__ __align__(16) __nv_bfloat16 g_pubTL[(size_t)KP * KPAD];
__device__ __align__(16) __nv_bfloat16 g_SH[NA * KPAD];
__device__ __align__(16) __nv_bfloat16 g_SL[NA * KPAD];
__device__ __align__(16) __nv_bfloat16 g_XH0[BD * KPAD];
__device__ __align__(16) __nv_bfloat16 g_XL0[BD * KPAD];
__device__ __align__(16) __nv_bfloat16 g_XH1[BD * KPAD];
__device__ __align__(16) __nv_bfloat16 g_XL1[BD * KPAD];
__device__ float g_Mp[(size_t)ZS * (MT * 128) * KPAD];  // merged partials
__device__ float g_S [NA * NA];
__device__ float g_Cm[BD * NA];
__device__ float g_X [BD * NA];
__device__ float g_v[NA], g_y[NA];
__device__ float g_lam, g_alpha;
__device__ float g_scale[BD];
__device__ unsigned int g_bar;

// ---------------- PTX helpers ----------------
__device__ __forceinline__ uint32_t smem_u32(const void* p) {
    uint32_t a;
    asm("{ .reg .u64 t; cvta.to.shared.u64 t, %1; cvt.u32.u64 %0, t; }" : "=r"(a) : "l"(p));
    return a;
}
__device__ __forceinline__ void ldsm4(uint32_t addr, uint32_t& r0, uint32_t& r1,
                                      uint32_t& r2, uint32_t& r3) {
    asm volatile("ldmatrix.sync.aligned.m8n8.x4.shared.b16 {%0,%1,%2,%3}, [%4];"
                 : "=r"(r0), "=r"(r1), "=r"(r2), "=r"(r3) : "r"(addr));
}
__device__ __forceinline__ void mma16816(float* c, const uint32_t* a, const uint32_t* b) {
    asm volatile(
        "mma.sync.aligned.m16n8k16.row.col.f32.bf16.bf16.f32 "
        "{%0,%1,%2,%3}, {%4,%5,%6,%7}, {%8,%9}, {%0,%1,%2,%3};"
        : "+f"(c[0]), "+f"(c[1]), "+f"(c[2]), "+f"(c[3])
        : "r"(a[0]), "r"(a[1]), "r"(a[2]), "r"(a[3]), "r"(b[0]), "r"(b[1]));
}
template <bool CG>
__device__ __forceinline__ void cpa16(uint32_t dst, const void* src, int srcsz) {
    if (CG)
        asm volatile("cp.async.cg.shared.global [%0], [%1], 16, %2;"
                     :: "r"(dst), "l"(src), "r"(srcsz));
    else
        asm volatile("cp.async.ca.shared.global [%0], [%1], 16, %2;"
                     :: "r"(dst), "l"(src), "r"(srcsz));
}
#define CP_COMMIT() asm volatile("cp.async.commit_group;" ::: "memory")

// async tile load: bf16 K-major rows; 512 uint4 per tile, 2 per thread.
// rows beyond `rows` are ZERO-filled (src-size 0 => zero fill).
template <bool CG>
__device__ __forceinline__ void ldt_async(const __nv_bfloat16* __restrict__ src, long long ld,
                                          int row0, int rows, int kb, uint32_t dst) {
    #pragma unroll
    for (int i = 0; i < 2; i++) {
        int e = threadIdx.x + i * 256;
        int r = e >> 2, q = e & 3;
        int gr = row0 + r;
        int sz = (gr < rows) ? 16 : 0;
        int rr = (gr < rows) ? gr : (rows - 1);
        cpa16<CG>(dst + r * 80 + q * 16, &src[(long long)rr * ld + kb + q * 8], sz);
    }
}

// ---------------------------------------------------------------------------
// Shared pipelined mainloop: acc += A[m0.., kb0..] * B[n0.., kb0..]^T
// bf16 hi/lo split: full3 ? (AhBh+AhBl+AlBh) : (AhBh+AhBl, Al never loaded).
// cp.async 2-stage double buffer.
// ---------------------------------------------------------------------------
template <bool CG>
__device__ __forceinline__ void gemm_mainloop(
    const __nv_bfloat16* __restrict__ Ah, const __nv_bfloat16* __restrict__ Al,
    long long lda, int Mrows, int m0,
    const __nv_bfloat16* __restrict__ Bh, const __nv_bfloat16* __restrict__ Bl,
    long long ldb, int Nrows, int n0,
    int kb0, int nch, uint32_t sbase, float acc[2][8][4], bool full3)
{
    const int lane = threadIdx.x & 31, wid = threadIdx.x >> 5;
    const int wm = wid >> 1, wn = wid & 1;
    const int aRow = wm * 32 + (lane & 15);
    const int aKof = (lane >> 4) * 8;
    const int bRowBase = wn * 64 + (lane & 7) + ((lane >> 4) << 3);
    const int bKof = ((lane >> 3) & 1) << 3;

    // prologue: stage 0
    {
        const int kb = kb0;
        ldt_async<CG>(Ah, lda, m0, Mrows, kb, sbase);
        if (full3) ldt_async<CG>(Al, lda, m0, Mrows, kb, sbase + TILE_B);
        ldt_async<CG>(Bh, ldb, n0, Nrows, kb, sbase + 2 * TILE_B);
        ldt_async<CG>(Bl, ldb, n0, Nrows, kb, sbase + 3 * TILE_B);
        CP_COMMIT();
    }
    for (int c = 0; c < nch; c++) {
        if (c + 1 < nch) {
            const int kb = kb0 + (c + 1) * 32;
            const uint32_t st = sbase + ((c + 1) & 1) * STAGE_B;
            ldt_async<CG>(Ah, lda, m0, Mrows, kb, st);
            if (full3) ldt_async<CG>(Al, lda, m0, Mrows, kb, st + TILE_B);
            ldt_async<CG>(Bh, ldb, n0, Nrows, kb, st + 2 * TILE_B);
            ldt_async<CG>(Bl, ldb, n0, Nrows, kb, st + 3 * TILE_B);
            CP_COMMIT();
            asm volatile("cp.async.wait_group 1;" ::: "memory");
        } else {
            asm volatile("cp.async.wait_group 0;" ::: "memory");
        }
        __syncthreads();

        const uint32_t uS = sbase + (c & 1) * STAGE_B;
        const uint32_t uAh = uS, uAl = uS + TILE_B;
        const uint32_t uBh = uS + 2 * TILE_B, uBl = uS + 3 * TILE_B;
        #pragma unroll
        for (int ks = 0; ks < 2; ks++) {
            uint32_t ah[2][4], al[2][4];
            #pragma unroll
            for (int mf = 0; mf < 2; mf++) {
                uint32_t ao = (uint32_t)((aRow + mf * 16) * 80 + (ks * 16 + aKof) * 2);
                ldsm4(uAh + ao, ah[mf][0], ah[mf][1], ah[mf][2], ah[mf][3]);
                if (full3)
                    ldsm4(uAl + ao, al[mf][0], al[mf][1], al[mf][2], al[mf][3]);
            }
            #pragma unroll
            for (int nf2 = 0; nf2 < 4; nf2++) {
                uint32_t bh[4], bl[4];
                uint32_t bo = (uint32_t)((bRowBase + nf2 * 16) * 80 + (ks * 16 + bKof) * 2);
                ldsm4(uBh + bo, bh[0], bh[1], bh[2], bh[3]);
                ldsm4(uBl + bo, bl[0], bl[1], bl[2], bl[3]);
                #pragma unroll
                for (int h = 0; h < 2; h++) {
                    const int nf = nf2 * 2 + h;
                    uint32_t* bhp = &bh[h * 2];
                    uint32_t* blp = &bl[h * 2];
                    #pragma unroll
                    for (int mf = 0; mf < 2; mf++) {
                        mma16816(acc[mf][nf], ah[mf], bhp);
                        mma16816(acc[mf][nf], ah[mf], blp);
                        if (full3) mma16816(acc[mf][nf], al[mf], bhp);
                    }
                }
            }
        }
        __syncthreads();
    }
}

// ---------------------------------------------------------------------------
// GEMM kernel.
// triN > 0: merged S+C form — row tiles by < triN are triangular (skip bx>by)
//           AND use the cheaper 2-pass split; by >= triN use full 3-pass.
// mode 0: partial store to outp + z*sliceStride
// mode 1: out = aux2[m]*t + clamp(aux[m,n]-t, +-1e-3)
// ---------------------------------------------------------------------------
__global__ void __launch_bounds__(256, 2)
gemm_tc(const __nv_bfloat16* __restrict__ Ah, const __nv_bfloat16* __restrict__ Al,
        long long lda, int Mrows,
        const __nv_bfloat16* __restrict__ Bh, const __nv_bfloat16* __restrict__ Bl,
        long long ldb, int Nrows,
        int K, int chunksPer,
        float* __restrict__ outp, long long sliceStride, long long ldc,
        int mode, const float* __restrict__ aux, long long ldaux,
        const float* __restrict__ aux2, int triN)
{
    const bool triTile = (triN > 0) && ((int)blockIdx.y < triN);
    if (triTile && blockIdx.x > blockIdx.y) return;
    const bool full3 = !triTile;

    const int m0 = blockIdx.y * 128, n0 = blockIdx.x * 128, z = blockIdx.z;
    const int kb0 = z * chunksPer * 32;
    const int kend = min(K, kb0 + chunksPer * 32);
    if (kb0 >= kend) return;
    const int nch = (kend - kb0) >> 5;

    extern __shared__ __align__(16) char smem[];
    const uint32_t sbase = smem_u32(smem);
    const int lane = threadIdx.x & 31, wid = threadIdx.x >> 5;
    const int wm = wid >> 1, wn = wid & 1;

    float acc[2][8][4];
    #pragma unroll
    for (int i = 0; i < 2; i++)
        #pragma unroll
        for (int j = 0; j < 8; j++)
            #pragma unroll
            for (int q = 0; q < 4; q++) acc[i][j][q] = 0.f;

    gemm_mainloop<false>(Ah, Al, lda, Mrows, m0, Bh, Bl, ldb, Nrows, n0,
                         kb0, nch, sbase, acc, full3);

    float* po = outp + (size_t)z * (size_t)sliceStride;
    #pragma unroll
    for (int mf = 0; mf < 2; mf++) {
        #pragma unroll
        for (int hh = 0; hh < 2; hh++) {
            const int m = m0 + wm * 32 + mf * 16 + (lane >> 2) + hh * 8;
            if (m >= Mrows) continue;
            const float sc = (mode == 1) ? aux2[m] : 0.f;
            #pragma unroll
            for (int nf = 0; nf < 8; nf++) {
                const int nb = n0 + wn * 64 + nf * 8 + (lane & 3) * 2;
                #pragma unroll
                for (int j = 0; j < 2; j++) {
                    const int n = nb + j;
                    if (n >= Nrows) continue;
                    const float t = acc[mf][nf][hh * 2 + j];
                    size_t ix = (size_t)m * ldc + n;
                    if (mode == 1) {
                        float rr = aux[(size_t)m * ldaux + n] - t;
                        rr = fminf(fmaxf(rr, -1e-3f), 1e-3f);
                        po[ix] = sc * t + rr;
                    } else {
                        po[ix] = t;
                    }
                }
            }
        }
    }
}

// ---------------------------------------------------------------------------
// Persistent solve kernel: initX + RICH_ITERS Richardson + clip scale.
// 16 CTAs, monotonic grid barrier (g_bar reset by zerobar_k earlier).
// ---------------------------------------------------------------------------
__device__ __forceinline__ void gridbar(unsigned int k) {
    __syncthreads();
    if (threadIdx.x == 0) {
        unsigned int* bar = &g_bar;
        asm volatile("red.release.gpu.global.add.u32 [%0], 1;" :: "l"(bar) : "memory");
        unsigned int target = NCTA_SOLVE * k;
        unsigned int cur;
        do {
            asm volatile("ld.acquire.gpu.global.u32 %0, [%1];" : "=r"(cur) : "l"(bar) : "memory");
            if (cur >= target) break;
            __nanosleep(64);
        } while (true);
    }
    __syncthreads();
}

__global__ void __launch_bounds__(256, 2) solve_k()
{
    extern __shared__ __align__(16) char smem[];
    const uint32_t sbase = smem_u32(smem);
    const int bx = blockIdx.x;
    const int mt = bx >> 3, nt = bx & 7;
    const int m0 = mt * 128, n0 = nt * 128;
    const int tid = threadIdx.x, lane = tid & 31, wid = tid >> 5;
    const int wm = wid >> 1, wn = wid & 1;
    const float alpha = g_alpha;

    // initX: X = alpha*C, + bf16 split into ping buffer 0
    #pragma unroll 4
    for (int e = 0; e < 64; e++) {
        int idx = tid + e * 256;
        int m = m0 + (idx >> 7), n = n0 + (idx & 127);
        if (n < NA) {
            float v = alpha * g_Cm[m * NA + n];
            g_X[m * NA + n] = v;
            __nv_bfloat16 h = __float2bfloat16(v);
            g_XH0[(size_t)m * KPAD + n] = h;
            g_XL0[(size_t)m * KPAD + n] = __float2bfloat16(v - __bfloat162float(h));
        }
    }
    gridbar(1);

    for (int t = 0; t < RICH_ITERS; t++) {
        const __nv_bfloat16* inH = (t & 1) ? g_XH1 : g_XH0;
        const __nv_bfloat16* inL = (t & 1) ? g_XL1 : g_XL0;
        __nv_bfloat16* outH = (t & 1) ? g_XH0 : g_XH1;
        __nv_bfloat16* outL = (t & 1) ? g_XL0 : g_XL1;

        float acc[2][8][4];
        #pragma unroll
        for (int i = 0; i < 2; i++)
            #pragma unroll
            for (int j = 0; j < 8; j++)
                #pragma unroll
                for (int q = 0; q < 4; q++) acc[i][j][q] = 0.f;

        gemm_mainloop<true>(inH, inL, KPAD, BD, m0, g_SH, g_SL, KPAD, NA, n0,
                            0, KPAD / 32, sbase, acc, true);

        #pragma unroll
        for (int mf = 0; mf < 2; mf++) {
            #pragma unroll
            for (int hh = 0; hh < 2; hh++) {
                const int m = m0 + wm * 32 + mf * 16 + (lane >> 2) + hh * 8;
                #pragma unroll
                for (int nf = 0; nf < 8; nf++) {
                    const int nb = n0 + wn * 64 + nf * 8 + (lane & 3) * 2;
                    #pragma unroll
                    for (int j = 0; j < 2; j++) {
                        const int n = nb + j;
                        if (n >= NA) continue;
                        const float tv = acc[mf][nf][hh * 2 + j];
                        const int ix = m * NA + n;
                        float xnew = g_X[ix] + alpha * (g_Cm[ix] - tv);
                        g_X[ix] = xnew;
                        __nv_bfloat16 h = __float2bfloat16(xnew);
                        outH[(size_t)m * KPAD + n] = h;
                        outL[(size_t)m * KPAD + n] =
                            __float2bfloat16(xnew - __bfloat162float(h));
                    }
                }
            }
        }
        gridbar(2 + t);
    }

    // clip scale: ||emb_i||^2 = X_i . C_i  (rows bx*16 .. bx*16+15, 2 per warp)
    #pragma unroll
    for (int s = 0; s < 2; s++) {
        const int row = bx * 16 + wid * 2 + s;
        float d = 0.f;
        for (int j = lane; j < NA; j += 32)
            d += g_X[row * NA + j] * g_Cm[row * NA + j];
        #pragma unroll
        for (int o = 16; o > 0; o >>= 1)
            d += __shfl_down_sync(0xffffffffu, d, o);
        if (lane == 0)
            g_scale[row] = fminf(rsqrtf(fmaxf(d, 1e-30f)), 1.0f);
    }
}

// ---------------- small kernels ----------------
// fused: pub fp32 -> allH/allL rows 0..NA-1 AND pubTH/pubTL (transposed, KPAD)
__global__ void transplit_pub_k(const float* __restrict__ pub)
{
    __shared__ float t[32][33];
    const int j0 = blockIdx.x * 32;   // KP dim
    const int i0 = blockIdx.y * 32;   // NA dim
    const int tx = threadIdx.x, ty = threadIdx.y;
    for (int r = ty; r < 32; r += 8) {
        const int i = i0 + r, j = j0 + tx;
        float v = 0.f;
        if (i < NA) {
            v = pub[(size_t)i * KP + j];
            __nv_bfloat16 h = __float2bfloat16(v);
            g_allH[(size_t)i * KP + j] = h;
            g_allL[(size_t)i * KP + j] = __float2bfloat16(v - __bfloat162float(h));
        }
        t[r][tx] = v;
    }
    __syncthreads();
    for (int r = ty; r < 32; r += 8) {
        const int n = j0 + r;     // pubT row (KP dim)
        const int k = i0 + tx;    // col (NA dim)
        if (k < NA) {
            const float v = t[tx][r];
            __nv_bfloat16 h = __float2bfloat16(v);
            g_pubTH[(size_t)n * KPAD + k] = h;
            g_pubTL[(size_t)n * KPAD + k] = __float2bfloat16(v - __bfloat162float(h));
        }
    }
}
__global__ void split_k(const float* __restrict__ s, __nv_bfloat16* __restrict__ h,
                        __nv_bfloat16* __restrict__ l, size_t n4) {
    size_t i = (size_t)blockIdx.x * blockDim.x + threadIdx.x;
    if (i < n4) {
        float4 v = ((const float4*)s)[i];
        float vv[4] = {v.x, v.y, v.z, v.w};
        #pragma unroll
        for (int j = 0; j < 4; j++) {
            __nv_bfloat16 hh = __float2bfloat16(vv[j]);
            h[i * 4 + j] = hh;
            l[i * 4 + j] = __float2bfloat16(vv[j] - __bfloat162float(hh));
        }
    }
}
__global__ void zerobar_k() { g_bar = 0u; }

// reduce merged partials: S (lower tri + mirror + bf16 split) and C rows.
__global__ void reduceSC_k() {
    const int idx = blockIdx.x * blockDim.x + threadIdx.x;
    const long long SLICE = (long long)(MT * 128) * KPAD;
    if (idx < NA * NA) {
        const int i = idx / NA, j = idx % NA;
        if (i >= j) {
            const long long base = (long long)i * KPAD + j;
            float s = 0.f;
            #pragma unroll
            for (int zz = 0; zz < ZS; zz++) s += g_Mp[zz * SLICE + base];
            g_S[i * NA + j] = s;
            g_S[j * NA + i] = s;
            __nv_bfloat16 h = __float2bfloat16(s);
            __nv_bfloat16 l = __float2bfloat16(s - __bfloat162float(h));
            g_SH[i * KPAD + j] = h; g_SL[i * KPAD + j] = l;
            g_SH[j * KPAD + i] = h; g_SL[j * KPAD + i] = l;
        }
    } else {
        const int r = idx - NA * NA;
        if (r < BD * NA) {
            const int m = r / NA, n = r % NA;
            const long long base = (long long)(NA + m) * KPAD + n;
            float s = 0.f;
            #pragma unroll
            for (int zz = 0; zz < ZS; zz++) s += g_Mp[zz * SLICE + base];
            g_Cm[m * NA + n] = s;
        }
    }
}
__global__ void initv_k() {
    int j = blockIdx.x * blockDim.x + threadIdx.x;
    if (j < NA) g_v[j] = g_S[j];
}
__global__ void matvec_k() {
    const int i = blockIdx.x;
    float s = 0.f;
    for (int j = threadIdx.x; j < NA; j += 256) s += g_S[i * NA + j] * g_v[j];
    __shared__ float sh[256];
    sh[threadIdx.x] = s; __syncthreads();
    for (int o = 128; o > 0; o >>= 1) {
        if (threadIdx.x < o) sh[threadIdx.x] += sh[threadIdx.x + o];
        __syncthreads();
    }
    if (threadIdx.x == 0) g_y[i] = sh[0];
}
__global__ void vnorm_k() {
    __shared__ float sh[256]; __shared__ float lam;
    float s = 0.f;
    for (int j = threadIdx.x; j < NA; j += 256) { float y = g_y[j]; s += y * y; }
    sh[threadIdx.x] = s; __syncthreads();
    for (int o = 128; o > 0; o >>= 1) {
        if (threadIdx.x < o) sh[threadIdx.x] += sh[threadIdx.x + o];
        __syncthreads();
    }
    if (threadIdx.x == 0) { lam = sqrtf(sh[0]); g_lam = lam; }
    __syncthreads();
    for (int j = threadIdx.x; j < NA; j += 256) g_v[j] = g_y[j] / lam;
}
__global__ void alpha_k() { g_alpha = 1.25f / g_lam; }

// ---------------------------------------------------------------------------
extern "C" void kernel_launch(void* const* d_in, const int* in_sizes, int n_in,
                              void* d_out, int out_size)
{
    const float* pub  = (const float*)d_in[0];
    const float* priv = (const float*)d_in[1];
    float* out = (float*)d_out;

    cudaFuncSetAttribute(gemm_tc, cudaFuncAttributeMaxDynamicSharedMemorySize, 2 * STAGE_B);
    cudaFuncSetAttribute(solve_k, cudaFuncAttributeMaxDynamicSharedMemorySize, 2 * STAGE_B);

    __nv_bfloat16 *allH, *allL, *pubTH, *pubTL, *XH1, *XL1;
    float *Mp, *scal;
    cudaGetSymbolAddress((void**)&allH, g_allH);
    cudaGetSymbolAddress((void**)&allL, g_allL);
    cudaGetSymbolAddress((void**)&pubTH, g_pubTH);
    cudaGetSymbolAddress((void**)&pubTL, g_pubTL);
    cudaGetSymbolAddress((void**)&XH1, g_XH1);
    cudaGetSymbolAddress((void**)&XL1, g_XL1);
    cudaGetSymbolAddress((void**)&Mp, g_Mp);
    cudaGetSymbolAddress((void**)&scal, g_scale);

    // 1) fused transpose + split of pub (rows 0..999 of all*, plus pubT)
    transplit_pub_k<<<dim3(KP / 32, 32), dim3(32, 8)>>>(pub);
    // 2) split priv into rows 1000..1255 of all*
    {
        size_t n4 = (size_t)BD * KP / 4;
        split_k<<<(unsigned)((n4 + 255) / 256), 256>>>(
            priv, allH + (size_t)NA * KP, allL + (size_t)NA * KP, n4);
    }
    zerobar_k<<<1, 1>>>();   // launch #3 -> merged GEMM is the profiled #4

    // 4) merged [S;C] = [pub;priv] * pub^T
    //    row tiles 0..6: triangular + 2-pass split; 7..9: full + 3-pass.
    //    split-K 6 -> 312 active CTAs.
    gemm_tc<<<dim3(8, MT, ZS), 256, 2 * STAGE_B>>>(
        allH, allL, KP, NAB, allH, allL, KP, NA,
        KP, 521, Mp, (long long)(MT * 128) * KPAD, KPAD,
        0, nullptr, 0, nullptr, NTRI);
    reduceSC_k<<<(NA * NA + BD * NA + 255) / 256, 256>>>();

    // 5) lambda_max via power iteration; alpha = 1.25/lam
    initv_k<<<4, 256>>>();
    for (int t = 0; t < POW_ITERS; t++) {
        matvec_k<<<NA, 256>>>();
        vnorm_k<<<1, 256>>>();
    }
    alpha_k<<<1, 1>>>();

    // 6) persistent solve: initX + 11 Richardson iters + clip scale (one launch)
    solve_k<<<NCTA_SOLVE, 256, 2 * STAGE_B>>>();

    // 7) out = scale*T + clamp(priv - T, +-1e-3), T = X*pub via pubT (pipelined)
    gemm_tc<<<dim3(782, 2, 1), 256, 2 * STAGE_B>>>(
        XH1, XL1, KPAD, BD, pubTH, pubTL, KPAD, KP,
        KPAD, KPAD / 32, out, 0, KP, 1, priv, KP, scal, 0);
}

// round 15
// speedup vs baseline: 1.0763x; 1.0763x over previous
#include <cuda_runtime.h>
#include <cuda_bf16.h>
#include <cstdint>
#include <math.h>

#define NA 1000
#define KP 100000
#define BD 256
#define KPAD 1024
#define RICH_ITERS 11
#define POW_ITERS 6
#define NCTA_SOLVE 16

// Tile: CTA 128x128, BK=32, 8 warps (4m x 2n), warp tile 32x64.
// Smem tile: 128 rows x 40 halves (32 data + 8 pad) = 10240 B; 4 tiles/stage.
#define TILE_B  10240
#define STAGE_B (4 * TILE_B)   // 40960

// ---------------- device scratch ----------------
__device__ __align__(16) __nv_bfloat16 g_pubH[(size_t)NA * KP];
__device__ __align__(16) __nv_bfloat16 g_pubL[(size_t)NA * KP];
__device__ __align__(16) __nv_bfloat16 g_privH[(size_t)BD * KP];
__device__ __align__(16) __nv_bfloat16 g_privL[(size_t)BD * KP];
__device__ __align__(16) __nv_bfloat16 g_SH[NA * KPAD];
__device__ __align__(16) __nv_bfloat16 g_SL[NA * KPAD];
__device__ __align__(16) __nv_bfloat16 g_XH0[BD * KPAD];
__device__ __align__(16) __nv_bfloat16 g_XL0[BD * KPAD];
__device__ __align__(16) __nv_bfloat16 g_XH1[BD * KPAD];
__device__ __align__(16) __nv_bfloat16 g_XL1[BD * KPAD];
__device__ float g_S [NA * NA];
__device__ float g_Sp[8][NA * NA];
__device__ float g_Cm[BD * NA];
__device__ float g_Cp[16][BD * NA];
__device__ float g_X [BD * NA];
__device__ float g_v[NA], g_y[NA];
__device__ float g_lam, g_alpha;
__device__ float g_scale[BD];
__device__ unsigned int g_bar;

// ---------------- PTX helpers ----------------
__device__ __forceinline__ uint32_t smem_u32(const void* p) {
    uint32_t a;
    asm("{ .reg .u64 t; cvta.to.shared.u64 t, %1; cvt.u32.u64 %0, t; }" : "=r"(a) : "l"(p));
    return a;
}
__device__ __forceinline__ void ldsm4(uint32_t addr, uint32_t& r0, uint32_t& r1,
                                      uint32_t& r2, uint32_t& r3) {
    asm volatile("ldmatrix.sync.aligned.m8n8.x4.shared.b16 {%0,%1,%2,%3}, [%4];"
                 : "=r"(r0), "=r"(r1), "=r"(r2), "=r"(r3) : "r"(addr));
}
__device__ __forceinline__ void mma16816(float* c, const uint32_t* a, const uint32_t* b) {
    asm volatile(
        "mma.sync.aligned.m16n8k16.row.col.f32.bf16.bf16.f32 "
        "{%0,%1,%2,%3}, {%4,%5,%6,%7}, {%8,%9}, {%0,%1,%2,%3};"
        : "+f"(c[0]), "+f"(c[1]), "+f"(c[2]), "+f"(c[3])
        : "r"(a[0]), "r"(a[1]), "r"(a[2]), "r"(a[3]), "r"(b[0]), "r"(b[1]));
}
template <bool CG>
__device__ __forceinline__ void cpa16(uint32_t dst, const void* src, int srcsz) {
    if (CG)
        asm volatile("cp.async.cg.shared.global [%0], [%1], 16, %2;"
                     :: "r"(dst), "l"(src), "r"(srcsz));
    else
        asm volatile("cp.async.ca.shared.global [%0], [%1], 16, %2;"
                     :: "r"(dst), "l"(src), "r"(srcsz));
}
#define CP_COMMIT() asm volatile("cp.async.commit_group;" ::: "memory")

// async tile load: bf16 K-major rows; 512 uint4 per tile, 2 per thread.
template <bool CG>
__device__ __forceinline__ void ldt_async(const __nv_bfloat16* __restrict__ src, long long ld,
                                          int row0, int rows, int kb, uint32_t dst) {
    #pragma unroll
    for (int i = 0; i < 2; i++) {
        int e = threadIdx.x + i * 256;
        int r = e >> 2, q = e & 3;
        int gr = row0 + r;
        int sz = (gr < rows) ? 16 : 0;
        int rr = (gr < rows) ? gr : (rows - 1);
        cpa16<CG>(dst + r * 80 + q * 16, &src[(long long)rr * ld + kb + q * 8], sz);
    }
}
// sync transposed fp32: B[n,k] = src[k, n0+n]; inline hi/lo split. (r8-validated)
__device__ __forceinline__ void ldtT(const float* __restrict__ src, int n0, int Nrows,
                                     int kb, char* dsth, char* dstl) {
    #pragma unroll
    for (int i = 0; i < 16; i++) {
        int idx = threadIdx.x + i * 256;
        int k = idx >> 7, n = idx & 127;
        float v = 0.f;
        if (kb + k < NA && n0 + n < Nrows)
            v = src[(long long)(kb + k) * KP + n0 + n];
        __nv_bfloat16 h = __float2bfloat16(v);
        __nv_bfloat16 l = __float2bfloat16(v - __bfloat162float(h));
        int off = n * 80 + k * 2;
        *(__nv_bfloat16*)(dsth + off) = h;
        *(__nv_bfloat16*)(dstl + off) = l;
    }
}

// ---------------------------------------------------------------------------
// Pipelined mainloop: acc += A[m0.., kb0..] * B[n0.., kb0..]^T
// full3 ? (AhBh+AhBl+AlBh) : (AhBh+AhBl, Al never loaded).
// ---------------------------------------------------------------------------
template <bool CG>
__device__ __forceinline__ void gemm_mainloop(
    const __nv_bfloat16* __restrict__ Ah, const __nv_bfloat16* __restrict__ Al,
    long long lda, int Mrows, int m0,
    const __nv_bfloat16* __restrict__ Bh, const __nv_bfloat16* __restrict__ Bl,
    long long ldb, int Nrows, int n0,
    int kb0, int nch, uint32_t sbase, float acc[2][8][4], bool full3)
{
    const int lane = threadIdx.x & 31, wid = threadIdx.x >> 5;
    const int wm = wid >> 1, wn = wid & 1;
    const int aRow = wm * 32 + (lane & 15);
    const int aKof = (lane >> 4) * 8;
    const int bRowBase = wn * 64 + (lane & 7) + ((lane >> 4) << 3);
    const int bKof = ((lane >> 3) & 1) << 3;

    {
        const int kb = kb0;
        ldt_async<CG>(Ah, lda, m0, Mrows, kb, sbase);
        if (full3) ldt_async<CG>(Al, lda, m0, Mrows, kb, sbase + TILE_B);
        ldt_async<CG>(Bh, ldb, n0, Nrows, kb, sbase + 2 * TILE_B);
        ldt_async<CG>(Bl, ldb, n0, Nrows, kb, sbase + 3 * TILE_B);
        CP_COMMIT();
    }
    for (int c = 0; c < nch; c++) {
        if (c + 1 < nch) {
            const int kb = kb0 + (c + 1) * 32;
            const uint32_t st = sbase + ((c + 1) & 1) * STAGE_B;
            ldt_async<CG>(Ah, lda, m0, Mrows, kb, st);
            if (full3) ldt_async<CG>(Al, lda, m0, Mrows, kb, st + TILE_B);
            ldt_async<CG>(Bh, ldb, n0, Nrows, kb, st + 2 * TILE_B);
            ldt_async<CG>(Bl, ldb, n0, Nrows, kb, st + 3 * TILE_B);
            CP_COMMIT();
            asm volatile("cp.async.wait_group 1;" ::: "memory");
        } else {
            asm volatile("cp.async.wait_group 0;" ::: "memory");
        }
        __syncthreads();

        const uint32_t uS = sbase + (c & 1) * STAGE_B;
        const uint32_t uAh = uS, uAl = uS + TILE_B;
        const uint32_t uBh = uS + 2 * TILE_B, uBl = uS + 3 * TILE_B;
        #pragma unroll
        for (int ks = 0; ks < 2; ks++) {
            uint32_t ah[2][4], al[2][4];
            #pragma unroll
            for (int mf = 0; mf < 2; mf++) {
                uint32_t ao = (uint32_t)((aRow + mf * 16) * 80 + (ks * 16 + aKof) * 2);
                ldsm4(uAh + ao, ah[mf][0], ah[mf][1], ah[mf][2], ah[mf][3]);
                if (full3)
                    ldsm4(uAl + ao, al[mf][0], al[mf][1], al[mf][2], al[mf][3]);
            }
            #pragma unroll
            for (int nf2 = 0; nf2 < 4; nf2++) {
                uint32_t bh[4], bl[4];
                uint32_t bo = (uint32_t)((bRowBase + nf2 * 16) * 80 + (ks * 16 + bKof) * 2);
                ldsm4(uBh + bo, bh[0], bh[1], bh[2], bh[3]);
                ldsm4(uBl + bo, bl[0], bl[1], bl[2], bl[3]);
                #pragma unroll
                for (int h = 0; h < 2; h++) {
                    const int nf = nf2 * 2 + h;
                    uint32_t* bhp = &bh[h * 2];
                    uint32_t* blp = &bl[h * 2];
                    #pragma unroll
                    for (int mf = 0; mf < 2; mf++) {
                        mma16816(acc[mf][nf], ah[mf], bhp);
                        mma16816(acc[mf][nf], ah[mf], blp);
                        if (full3) mma16816(acc[mf][nf], al[mf], bhp);
                    }
                }
            }
        }
        __syncthreads();
    }
}

// ---------------------------------------------------------------------------
// GEMM kernel. BT=0: bf16 B, pipelined. BT=1: B transposed inline from fp32.
// tri=1 (BT=0 only): triangular skip AND 2-pass split (S is error-tolerant).
// mode 0: partial store; mode 1: clamp epilogue.
// ---------------------------------------------------------------------------
template <int BT>
__global__ void __launch_bounds__(256, 2)
gemm_tc(const __nv_bfloat16* __restrict__ Ah, const __nv_bfloat16* __restrict__ Al,
        long long lda, int Mrows,
        const __nv_bfloat16* __restrict__ Bh, const __nv_bfloat16* __restrict__ Bl,
        const float* __restrict__ Bsrc, long long ldb, int Nrows,
        int K, int chunksPer,
        float* __restrict__ outp, long long sliceStride, long long ldc,
        int mode, const float* __restrict__ aux, long long ldaux,
        const float* __restrict__ aux2, int tri)
{
    if (tri && blockIdx.x > blockIdx.y) return;
    const bool full3 = (BT == 1) || !tri;
    const int m0 = blockIdx.y * 128, n0 = blockIdx.x * 128, z = blockIdx.z;
    const int kb0 = z * chunksPer * 32;
    const int kend = min(K, kb0 + chunksPer * 32);
    if (kb0 >= kend) return;
    const int nch = (kend - kb0) >> 5;

    extern __shared__ __align__(16) char smem[];
    const uint32_t sbase = smem_u32(smem);
    const int lane = threadIdx.x & 31, wid = threadIdx.x >> 5;
    const int wm = wid >> 1, wn = wid & 1;

    float acc[2][8][4];
    #pragma unroll
    for (int i = 0; i < 2; i++)
        #pragma unroll
        for (int j = 0; j < 8; j++)
            #pragma unroll
            for (int q = 0; q < 4; q++) acc[i][j][q] = 0.f;

    if (BT == 0) {
        gemm_mainloop<false>(Ah, Al, lda, Mrows, m0, Bh, Bl, ldb, Nrows, n0,
                             kb0, nch, sbase, acc, full3);
    } else {
        // r8-validated sync path: A bf16 loads + inline fp32 transpose for B.
        char* sAh = smem;
        char* sAl = smem + TILE_B;
        char* sBh = smem + 2 * TILE_B;
        char* sBl = smem + 3 * TILE_B;
        const uint32_t uAh = sbase, uAl = sbase + TILE_B;
        const uint32_t uBh = sbase + 2 * TILE_B, uBl = sbase + 3 * TILE_B;
        const int aRow = wm * 32 + (lane & 15);
        const int aKof = (lane >> 4) * 8;
        const int bRowBase = wn * 64 + (lane & 7) + ((lane >> 4) << 3);
        const int bKof = ((lane >> 3) & 1) << 3;
        for (int c = 0; c < nch; c++) {
            const int kb = kb0 + c * 32;
            __syncthreads();
            #pragma unroll
            for (int i = 0; i < 2; i++) {
                int e = threadIdx.x + i * 256;
                int r = e >> 2, q = e & 3;
                uint4 vh = make_uint4(0, 0, 0, 0), vl = make_uint4(0, 0, 0, 0);
                if (m0 + r < Mrows) {
                    vh = *(const uint4*)&Ah[(long long)(m0 + r) * lda + kb + q * 8];
                    vl = *(const uint4*)&Al[(long long)(m0 + r) * lda + kb + q * 8];
                }
                *(uint4*)(sAh + r * 80 + q * 16) = vh;
                *(uint4*)(sAl + r * 80 + q * 16) = vl;
            }
            ldtT(Bsrc, n0, Nrows, kb, sBh, sBl);
            __syncthreads();
            #pragma unroll
            for (int ks = 0; ks < 2; ks++) {
                uint32_t ah[2][4], al[2][4];
                #pragma unroll
                for (int mf = 0; mf < 2; mf++) {
                    uint32_t ao = (uint32_t)((aRow + mf * 16) * 80 + (ks * 16 + aKof) * 2);
                    ldsm4(uAh + ao, ah[mf][0], ah[mf][1], ah[mf][2], ah[mf][3]);
                    ldsm4(uAl + ao, al[mf][0], al[mf][1], al[mf][2], al[mf][3]);
                }
                #pragma unroll
                for (int nf2 = 0; nf2 < 4; nf2++) {
                    uint32_t bh[4], bl[4];
                    uint32_t bo = (uint32_t)((bRowBase + nf2 * 16) * 80 + (ks * 16 + bKof) * 2);
                    ldsm4(uBh + bo, bh[0], bh[1], bh[2], bh[3]);
                    ldsm4(uBl + bo, bl[0], bl[1], bl[2], bl[3]);
                    #pragma unroll
                    for (int h = 0; h < 2; h++) {
                        const int nf = nf2 * 2 + h;
                        uint32_t* bhp = &bh[h * 2];
                        uint32_t* blp = &bl[h * 2];
                        #pragma unroll
                        for (int mf = 0; mf < 2; mf++) {
                            mma16816(acc[mf][nf], ah[mf], bhp);
                            mma16816(acc[mf][nf], ah[mf], blp);
                            mma16816(acc[mf][nf], al[mf], bhp);
                        }
                    }
                }
            }
        }
    }

    float* po = outp + (size_t)z * (size_t)sliceStride;
    #pragma unroll
    for (int mf = 0; mf < 2; mf++) {
        #pragma unroll
        for (int hh = 0; hh < 2; hh++) {
            const int m = m0 + wm * 32 + mf * 16 + (lane >> 2) + hh * 8;
            if (m >= Mrows) continue;
            const float sc = (mode == 1) ? aux2[m] : 0.f;
            #pragma unroll
            for (int nf = 0; nf < 8; nf++) {
                const int nb = n0 + wn * 64 + nf * 8 + (lane & 3) * 2;
                #pragma unroll
                for (int j = 0; j < 2; j++) {
                    const int n = nb + j;
                    if (n >= Nrows) continue;
                    const float t = acc[mf][nf][hh * 2 + j];
                    size_t ix = (size_t)m * ldc + n;
                    if (mode == 1) {
                        float rr = aux[(size_t)m * ldaux + n] - t;
                        rr = fminf(fmaxf(rr, -1e-3f), 1e-3f);
                        po[ix] = sc * t + rr;
                    } else {
                        po[ix] = t;
                    }
                }
            }
        }
    }
}

// ---------------------------------------------------------------------------
// Persistent solve kernel (r12/r14-validated).
// ---------------------------------------------------------------------------
__device__ __forceinline__ void gridbar(unsigned int k) {
    __syncthreads();
    if (threadIdx.x == 0) {
        unsigned int* bar = &g_bar;
        asm volatile("red.release.gpu.global.add.u32 [%0], 1;" :: "l"(bar) : "memory");
        unsigned int target = NCTA_SOLVE * k;
        unsigned int cur;
        do {
            asm volatile("ld.acquire.gpu.global.u32 %0, [%1];" : "=r"(cur) : "l"(bar) : "memory");
            if (cur >= target) break;
            __nanosleep(64);
        } while (true);
    }
    __syncthreads();
}

__global__ void __launch_bounds__(256, 2) solve_k()
{
    extern __shared__ __align__(16) char smem[];
    const uint32_t sbase = smem_u32(smem);
    const int bx = blockIdx.x;
    const int mt = bx >> 3, nt = bx & 7;
    const int m0 = mt * 128, n0 = nt * 128;
    const int tid = threadIdx.x, lane = tid & 31, wid = tid >> 5;
    const int wm = wid >> 1, wn = wid & 1;
    const float alpha = g_alpha;

    #pragma unroll 4
    for (int e = 0; e < 64; e++) {
        int idx = tid + e * 256;
        int m = m0 + (idx >> 7), n = n0 + (idx & 127);
        if (n < NA) {
            float v = alpha * g_Cm[m * NA + n];
            g_X[m * NA + n] = v;
            __nv_bfloat16 h = __float2bfloat16(v);
            g_XH0[(size_t)m * KPAD + n] = h;
            g_XL0[(size_t)m * KPAD + n] = __float2bfloat16(v - __bfloat162float(h));
        }
    }
    gridbar(1);

    for (int t = 0; t < RICH_ITERS; t++) {
        const __nv_bfloat16* inH = (t & 1) ? g_XH1 : g_XH0;
        const __nv_bfloat16* inL = (t & 1) ? g_XL1 : g_XL0;
        __nv_bfloat16* outH = (t & 1) ? g_XH0 : g_XH1;
        __nv_bfloat16* outL = (t & 1) ? g_XL0 : g_XL1;

        float acc[2][8][4];
        #pragma unroll
        for (int i = 0; i < 2; i++)
            #pragma unroll
            for (int j = 0; j < 8; j++)
                #pragma unroll
                for (int q = 0; q < 4; q++) acc[i][j][q] = 0.f;

        gemm_mainloop<true>(inH, inL, KPAD, BD, m0, g_SH, g_SL, KPAD, NA, n0,
                            0, KPAD / 32, sbase, acc, true);

        #pragma unroll
        for (int mf = 0; mf < 2; mf++) {
            #pragma unroll
            for (int hh = 0; hh < 2; hh++) {
                const int m = m0 + wm * 32 + mf * 16 + (lane >> 2) + hh * 8;
                #pragma unroll
                for (int nf = 0; nf < 8; nf++) {
                    const int nb = n0 + wn * 64 + nf * 8 + (lane & 3) * 2;
                    #pragma unroll
                    for (int j = 0; j < 2; j++) {
                        const int n = nb + j;
                        if (n >= NA) continue;
                        const float tv = acc[mf][nf][hh * 2 + j];
                        const int ix = m * NA + n;
                        float xnew = g_X[ix] + alpha * (g_Cm[ix] - tv);
                        g_X[ix] = xnew;
                        __nv_bfloat16 h = __float2bfloat16(xnew);
                        outH[(size_t)m * KPAD + n] = h;
                        outL[(size_t)m * KPAD + n] =
                            __float2bfloat16(xnew - __bfloat162float(h));
                    }
                }
            }
        }
        gridbar(2 + t);
    }

    #pragma unroll
    for (int s = 0; s < 2; s++) {
        const int row = bx * 16 + wid * 2 + s;
        float d = 0.f;
        for (int j = lane; j < NA; j += 32)
            d += g_X[row * NA + j] * g_Cm[row * NA + j];
        #pragma unroll
        for (int o = 16; o > 0; o >>= 1)
            d += __shfl_down_sync(0xffffffffu, d, o);
        if (lane == 0)
            g_scale[row] = fminf(rsqrtf(fmaxf(d, 1e-30f)), 1.0f);
    }
}

// ---------------- small kernels ----------------
__global__ void split_k(const float* __restrict__ s, __nv_bfloat16* __restrict__ h,
                        __nv_bfloat16* __restrict__ l, size_t n4) {
    size_t i = (size_t)blockIdx.x * blockDim.x + threadIdx.x;
    if (i < n4) {
        float4 v = ((const float4*)s)[i];
        float vv[4] = {v.x, v.y, v.z, v.w};
        #pragma unroll
        for (int j = 0; j < 4; j++) {
            __nv_bfloat16 hh = __float2bfloat16(vv[j]);
            h[i * 4 + j] = hh;
            l[i * 4 + j] = __float2bfloat16(vv[j] - __bfloat162float(hh));
        }
    }
}
__global__ void zerobar_k() { g_bar = 0u; }

__global__ void reduceS_split_k() {
    int idx = blockIdx.x * blockDim.x + threadIdx.x;
    if (idx < NA * NA) {
        int i = idx / NA, j = idx % NA;
        if (i >= j) {
            float s = 0.f;
            #pragma unroll
            for (int zz = 0; zz < 8; zz++) s += g_Sp[zz][idx];
            g_S[i * NA + j] = s;
            g_S[j * NA + i] = s;
            __nv_bfloat16 h = __float2bfloat16(s);
            __nv_bfloat16 l = __float2bfloat16(s - __bfloat162float(h));
            g_SH[i * KPAD + j] = h; g_SL[i * KPAD + j] = l;
            g_SH[j * KPAD + i] = h; g_SL[j * KPAD + i] = l;
        }
    }
}
__global__ void reduceC_k() {
    int idx = blockIdx.x * blockDim.x + threadIdx.x;
    if (idx < BD * NA) {
        float s = 0.f;
        #pragma unroll
        for (int zz = 0; zz < 16; zz++) s += g_Cp[zz][idx];
        g_Cm[idx] = s;
    }
}
__global__ void initv_k() {
    int j = blockIdx.x * blockDim.x + threadIdx.x;
    if (j < NA) g_v[j] = g_S[j];
}
__global__ void matvec_k() {
    const int i = blockIdx.x;
    float s = 0.f;
    for (int j = threadIdx.x; j < NA; j += 256) s += g_S[i * NA + j] * g_v[j];
    __shared__ float sh[256];
    sh[threadIdx.x] = s; __syncthreads();
    for (int o = 128; o > 0; o >>= 1) {
        if (threadIdx.x < o) sh[threadIdx.x] += sh[threadIdx.x + o];
        __syncthreads();
    }
    if (threadIdx.x == 0) g_y[i] = sh[0];
}
__global__ void vnorm_k() {
    __shared__ float sh[256]; __shared__ float lam;
    float s = 0.f;
    for (int j = threadIdx.x; j < NA; j += 256) { float y = g_y[j]; s += y * y; }
    sh[threadIdx.x] = s; __syncthreads();
    for (int o = 128; o > 0; o >>= 1) {
        if (threadIdx.x < o) sh[threadIdx.x] += sh[threadIdx.x + o];
        __syncthreads();
    }
    if (threadIdx.x == 0) { lam = sqrtf(sh[0]); g_lam = lam; }
    __syncthreads();
    for (int j = threadIdx.x; j < NA; j += 256) g_v[j] = g_y[j] / lam;
}
__global__ void alpha_k() { g_alpha = 1.25f / g_lam; }

// ---------------------------------------------------------------------------
extern "C" void kernel_launch(void* const* d_in, const int* in_sizes, int n_in,
                              void* d_out, int out_size)
{
    const float* pub  = (const float*)d_in[0];
    const float* priv = (const float*)d_in[1];
    float* out = (float*)d_out;

    cudaFuncSetAttribute(gemm_tc<0>, cudaFuncAttributeMaxDynamicSharedMemorySize, 2 * STAGE_B);
    cudaFuncSetAttribute(gemm_tc<1>, cudaFuncAttributeMaxDynamicSharedMemorySize, 2 * STAGE_B);
    cudaFuncSetAttribute(solve_k, cudaFuncAttributeMaxDynamicSharedMemorySize, 2 * STAGE_B);

    __nv_bfloat16 *pubH, *pubL, *privH, *privL, *XH1, *XL1;
    float *Sp, *Cp, *scal;
    cudaGetSymbolAddress((void**)&pubH, g_pubH);
    cudaGetSymbolAddress((void**)&pubL, g_pubL);
    cudaGetSymbolAddress((void**)&privH, g_privH);
    cudaGetSymbolAddress((void**)&privL, g_privL);
    cudaGetSymbolAddress((void**)&XH1, g_XH1);
    cudaGetSymbolAddress((void**)&XL1, g_XL1);
    cudaGetSymbolAddress((void**)&Sp, g_Sp);
    cudaGetSymbolAddress((void**)&Cp, g_Cp);
    cudaGetSymbolAddress((void**)&scal, g_scale);

    // 1) split pub; 2) split priv; 3) barrier reset (launch #3)
    {
        size_t n4 = (size_t)NA * KP / 4;
        split_k<<<(unsigned)((n4 + 255) / 256), 256>>>(pub, pubH, pubL, n4);
        n4 = (size_t)BD * KP / 4;
        split_k<<<(unsigned)((n4 + 255) / 256), 256>>>(priv, privH, privL, n4);
    }
    zerobar_k<<<1, 1>>>();

    // 4) S = pub*pub^T — tri blocks + 2-PASS split (error-tolerant), split-K 8.
    //    288 active CTAs, profiled launch #4.
    gemm_tc<0><<<dim3(8, 8, 8), 256, 2 * STAGE_B>>>(
        pubH, pubL, KP, NA, pubH, pubL, nullptr, KP, NA,
        KP, 391, Sp, (long long)NA * NA, NA, 0, nullptr, 0, nullptr, 1);
    reduceS_split_k<<<(NA * NA + 255) / 256, 256>>>();

    // 5) C = priv*pub^T — full 3-pass, split-K 16 (256 CTAs).
    gemm_tc<0><<<dim3(8, 2, 16), 256, 2 * STAGE_B>>>(
        privH, privL, KP, BD, pubH, pubL, nullptr, KP, NA,
        KP, 196, Cp, (long long)BD * NA, NA, 0, nullptr, 0, nullptr, 0);
    reduceC_k<<<(BD * NA + 255) / 256, 256>>>();

    // 6) lambda_max via power iteration; alpha = 1.25/lam
    initv_k<<<4, 256>>>();
    for (int t = 0; t < POW_ITERS; t++) {
        matvec_k<<<NA, 256>>>();
        vnorm_k<<<1, 256>>>();
    }
    alpha_k<<<1, 1>>>();

    // 7) persistent solve (one launch)
    solve_k<<<NCTA_SOLVE, 256, 2 * STAGE_B>>>();

    // 8) out = scale*T + clamp(priv - T, +-1e-3), T = X*pub (inline transpose, r8 path)
    gemm_tc<1><<<dim3(782, 2, 1), 256, STAGE_B>>>(
        XH1, XL1, KPAD, BD, nullptr, nullptr, pub, KP, KP,
        KPAD, 32, out, 0, KP, 1, priv, KP, scal, 0);
}

// round 16
// speedup vs baseline: 1.3378x; 1.2429x over previous
#include <cuda_runtime.h>
#include <cuda_bf16.h>
#include <cstdint>
#include <math.h>

#define NA 1000
#define KP 100000
#define BD 256
#define KPAD 1024
#define RICH_ITERS 9
#define POW_ITERS 6
#define NCTA_SOLVE 128
#define ZSOLVE 8

// Tile: CTA 128x128, BK=32, 8 warps (4m x 2n), warp tile 32x64.
#define TILE_B  10240
#define STAGE_B (4 * TILE_B)   // 40960

// ---------------- device scratch ----------------
__device__ __align__(16) __nv_bfloat16 g_pubH[(size_t)NA * KP];
__device__ __align__(16) __nv_bfloat16 g_pubL[(size_t)NA * KP];
__device__ __align__(16) __nv_bfloat16 g_privH[(size_t)BD * KP];
__device__ __align__(16) __nv_bfloat16 g_privL[(size_t)BD * KP];
__device__ __align__(16) __nv_bfloat16 g_SH[NA * KPAD];
__device__ __align__(16) __nv_bfloat16 g_SL[NA * KPAD];
__device__ __align__(16) __nv_bfloat16 g_XH0[BD * KPAD];
__device__ __align__(16) __nv_bfloat16 g_XL0[BD * KPAD];
__device__ __align__(16) __nv_bfloat16 g_XH1[BD * KPAD];
__device__ __align__(16) __nv_bfloat16 g_XL1[BD * KPAD];
__device__ float g_S [NA * NA];
__device__ float g_Sp[8][NA * NA];
__device__ float g_Cm[BD * NA];
__device__ float g_Cp[16][BD * NA];
__device__ float g_Rp[ZSOLVE][BD * KPAD];   // solve split-K partials
__device__ float g_X [BD * NA];
__device__ float g_v[KPAD], g_y[KPAD];
__device__ float g_scale[BD];
__device__ unsigned int g_bar;

// ---------------- PTX helpers ----------------
__device__ __forceinline__ uint32_t smem_u32(const void* p) {
    uint32_t a;
    asm("{ .reg .u64 t; cvta.to.shared.u64 t, %1; cvt.u32.u64 %0, t; }" : "=r"(a) : "l"(p));
    return a;
}
__device__ __forceinline__ void ldsm4(uint32_t addr, uint32_t& r0, uint32_t& r1,
                                      uint32_t& r2, uint32_t& r3) {
    asm volatile("ldmatrix.sync.aligned.m8n8.x4.shared.b16 {%0,%1,%2,%3}, [%4];"
                 : "=r"(r0), "=r"(r1), "=r"(r2), "=r"(r3) : "r"(addr));
}
__device__ __forceinline__ void mma16816(float* c, const uint32_t* a, const uint32_t* b) {
    asm volatile(
        "mma.sync.aligned.m16n8k16.row.col.f32.bf16.bf16.f32 "
        "{%0,%1,%2,%3}, {%4,%5,%6,%7}, {%8,%9}, {%0,%1,%2,%3};"
        : "+f"(c[0]), "+f"(c[1]), "+f"(c[2]), "+f"(c[3])
        : "r"(a[0]), "r"(a[1]), "r"(a[2]), "r"(a[3]), "r"(b[0]), "r"(b[1]));
}
template <bool CG>
__device__ __forceinline__ void cpa16(uint32_t dst, const void* src, int srcsz) {
    if (CG)
        asm volatile("cp.async.cg.shared.global [%0], [%1], 16, %2;"
                     :: "r"(dst), "l"(src), "r"(srcsz));
    else
        asm volatile("cp.async.ca.shared.global [%0], [%1], 16, %2;"
                     :: "r"(dst), "l"(src), "r"(srcsz));
}
#define CP_COMMIT() asm volatile("cp.async.commit_group;" ::: "memory")

template <bool CG>
__device__ __forceinline__ void ldt_async(const __nv_bfloat16* __restrict__ src, long long ld,
                                          int row0, int rows, int kb, uint32_t dst) {
    #pragma unroll
    for (int i = 0; i < 2; i++) {
        int e = threadIdx.x + i * 256;
        int r = e >> 2, q = e & 3;
        int gr = row0 + r;
        int sz = (gr < rows) ? 16 : 0;
        int rr = (gr < rows) ? gr : (rows - 1);
        cpa16<CG>(dst + r * 80 + q * 16, &src[(long long)rr * ld + kb + q * 8], sz);
    }
}
// sync transposed fp32: B[n,k] = src[k, n0+n]; inline hi/lo split. (r8-validated)
__device__ __forceinline__ void ldtT(const float* __restrict__ src, int n0, int Nrows,
                                     int kb, char* dsth, char* dstl) {
    #pragma unroll
    for (int i = 0; i < 16; i++) {
        int idx = threadIdx.x + i * 256;
        int k = idx >> 7, n = idx & 127;
        float v = 0.f;
        if (kb + k < NA && n0 + n < Nrows)
            v = src[(long long)(kb + k) * KP + n0 + n];
        __nv_bfloat16 h = __float2bfloat16(v);
        __nv_bfloat16 l = __float2bfloat16(v - __bfloat162float(h));
        int off = n * 80 + k * 2;
        *(__nv_bfloat16*)(dsth + off) = h;
        *(__nv_bfloat16*)(dstl + off) = l;
    }
}

// ---------------------------------------------------------------------------
// Pipelined mainloop: acc += A[m0.., kb0..] * B[n0.., kb0..]^T
// full3 ? (AhBh+AhBl+AlBh) : (AhBh+AhBl, Al never loaded).
// ---------------------------------------------------------------------------
template <bool CG>
__device__ __forceinline__ void gemm_mainloop(
    const __nv_bfloat16* __restrict__ Ah, const __nv_bfloat16* __restrict__ Al,
    long long lda, int Mrows, int m0,
    const __nv_bfloat16* __restrict__ Bh, const __nv_bfloat16* __restrict__ Bl,
    long long ldb, int Nrows, int n0,
    int kb0, int nch, uint32_t sbase, float acc[2][8][4], bool full3)
{
    const int lane = threadIdx.x & 31, wid = threadIdx.x >> 5;
    const int wm = wid >> 1, wn = wid & 1;
    const int aRow = wm * 32 + (lane & 15);
    const int aKof = (lane >> 4) * 8;
    const int bRowBase = wn * 64 + (lane & 7) + ((lane >> 4) << 3);
    const int bKof = ((lane >> 3) & 1) << 3;

    {
        const int kb = kb0;
        ldt_async<CG>(Ah, lda, m0, Mrows, kb, sbase);
        if (full3) ldt_async<CG>(Al, lda, m0, Mrows, kb, sbase + TILE_B);
        ldt_async<CG>(Bh, ldb, n0, Nrows, kb, sbase + 2 * TILE_B);
        ldt_async<CG>(Bl, ldb, n0, Nrows, kb, sbase + 3 * TILE_B);
        CP_COMMIT();
    }
    for (int c = 0; c < nch; c++) {
        if (c + 1 < nch) {
            const int kb = kb0 + (c + 1) * 32;
            const uint32_t st = sbase + ((c + 1) & 1) * STAGE_B;
            ldt_async<CG>(Ah, lda, m0, Mrows, kb, st);
            if (full3) ldt_async<CG>(Al, lda, m0, Mrows, kb, st + TILE_B);
            ldt_async<CG>(Bh, ldb, n0, Nrows, kb, st + 2 * TILE_B);
            ldt_async<CG>(Bl, ldb, n0, Nrows, kb, st + 3 * TILE_B);
            CP_COMMIT();
            asm volatile("cp.async.wait_group 1;" ::: "memory");
        } else {
            asm volatile("cp.async.wait_group 0;" ::: "memory");
        }
        __syncthreads();

        const uint32_t uS = sbase + (c & 1) * STAGE_B;
        const uint32_t uAh = uS, uAl = uS + TILE_B;
        const uint32_t uBh = uS + 2 * TILE_B, uBl = uS + 3 * TILE_B;
        #pragma unroll
        for (int ks = 0; ks < 2; ks++) {
            uint32_t ah[2][4], al[2][4];
            #pragma unroll
            for (int mf = 0; mf < 2; mf++) {
                uint32_t ao = (uint32_t)((aRow + mf * 16) * 80 + (ks * 16 + aKof) * 2);
                ldsm4(uAh + ao, ah[mf][0], ah[mf][1], ah[mf][2], ah[mf][3]);
                if (full3)
                    ldsm4(uAl + ao, al[mf][0], al[mf][1], al[mf][2], al[mf][3]);
            }
            #pragma unroll
            for (int nf2 = 0; nf2 < 4; nf2++) {
                uint32_t bh[4], bl[4];
                uint32_t bo = (uint32_t)((bRowBase + nf2 * 16) * 80 + (ks * 16 + bKof) * 2);
                ldsm4(uBh + bo, bh[0], bh[1], bh[2], bh[3]);
                ldsm4(uBl + bo, bl[0], bl[1], bl[2], bl[3]);
                #pragma unroll
                for (int h = 0; h < 2; h++) {
                    const int nf = nf2 * 2 + h;
                    uint32_t* bhp = &bh[h * 2];
                    uint32_t* blp = &bl[h * 2];
                    #pragma unroll
                    for (int mf = 0; mf < 2; mf++) {
                        mma16816(acc[mf][nf], ah[mf], bhp);
                        mma16816(acc[mf][nf], ah[mf], blp);
                        if (full3) mma16816(acc[mf][nf], al[mf], bhp);
                    }
                }
            }
        }
        __syncthreads();
    }
}

// ---------------------------------------------------------------------------
// GEMM kernel (r15-validated). BT=0: bf16 B pipelined; BT=1: inline transpose.
// tri=1: triangular skip + 2-pass split. mode 0: partial store; 1: clamp.
// ---------------------------------------------------------------------------
template <int BT>
__global__ void __launch_bounds__(256, 2)
gemm_tc(const __nv_bfloat16* __restrict__ Ah, const __nv_bfloat16* __restrict__ Al,
        long long lda, int Mrows,
        const __nv_bfloat16* __restrict__ Bh, const __nv_bfloat16* __restrict__ Bl,
        const float* __restrict__ Bsrc, long long ldb, int Nrows,
        int K, int chunksPer,
        float* __restrict__ outp, long long sliceStride, long long ldc,
        int mode, const float* __restrict__ aux, long long ldaux,
        const float* __restrict__ aux2, int tri)
{
    if (tri && blockIdx.x > blockIdx.y) return;
    const bool full3 = (BT == 1) || !tri;
    const int m0 = blockIdx.y * 128, n0 = blockIdx.x * 128, z = blockIdx.z;
    const int kb0 = z * chunksPer * 32;
    const int kend = min(K, kb0 + chunksPer * 32);
    if (kb0 >= kend) return;
    const int nch = (kend - kb0) >> 5;

    extern __shared__ __align__(16) char smem[];
    const uint32_t sbase = smem_u32(smem);
    const int lane = threadIdx.x & 31, wid = threadIdx.x >> 5;
    const int wm = wid >> 1, wn = wid & 1;

    float acc[2][8][4];
    #pragma unroll
    for (int i = 0; i < 2; i++)
        #pragma unroll
        for (int j = 0; j < 8; j++)
            #pragma unroll
            for (int q = 0; q < 4; q++) acc[i][j][q] = 0.f;

    if (BT == 0) {
        gemm_mainloop<false>(Ah, Al, lda, Mrows, m0, Bh, Bl, ldb, Nrows, n0,
                             kb0, nch, sbase, acc, full3);
    } else {
        char* sAh = smem;
        char* sAl = smem + TILE_B;
        char* sBh = smem + 2 * TILE_B;
        char* sBl = smem + 3 * TILE_B;
        const uint32_t uAh = sbase, uAl = sbase + TILE_B;
        const uint32_t uBh = sbase + 2 * TILE_B, uBl = sbase + 3 * TILE_B;
        const int aRow = wm * 32 + (lane & 15);
        const int aKof = (lane >> 4) * 8;
        const int bRowBase = wn * 64 + (lane & 7) + ((lane >> 4) << 3);
        const int bKof = ((lane >> 3) & 1) << 3;
        for (int c = 0; c < nch; c++) {
            const int kb = kb0 + c * 32;
            __syncthreads();
            #pragma unroll
            for (int i = 0; i < 2; i++) {
                int e = threadIdx.x + i * 256;
                int r = e >> 2, q = e & 3;
                uint4 vh = make_uint4(0, 0, 0, 0), vl = make_uint4(0, 0, 0, 0);
                if (m0 + r < Mrows) {
                    vh = *(const uint4*)&Ah[(long long)(m0 + r) * lda + kb + q * 8];
                    vl = *(const uint4*)&Al[(long long)(m0 + r) * lda + kb + q * 8];
                }
                *(uint4*)(sAh + r * 80 + q * 16) = vh;
                *(uint4*)(sAl + r * 80 + q * 16) = vl;
            }
            ldtT(Bsrc, n0, Nrows, kb, sBh, sBl);
            __syncthreads();
            #pragma unroll
            for (int ks = 0; ks < 2; ks++) {
                uint32_t ah[2][4], al[2][4];
                #pragma unroll
                for (int mf = 0; mf < 2; mf++) {
                    uint32_t ao = (uint32_t)((aRow + mf * 16) * 80 + (ks * 16 + aKof) * 2);
                    ldsm4(uAh + ao, ah[mf][0], ah[mf][1], ah[mf][2], ah[mf][3]);
                    ldsm4(uAl + ao, al[mf][0], al[mf][1], al[mf][2], al[mf][3]);
                }
                #pragma unroll
                for (int nf2 = 0; nf2 < 4; nf2++) {
                    uint32_t bh[4], bl[4];
                    uint32_t bo = (uint32_t)((bRowBase + nf2 * 16) * 80 + (ks * 16 + bKof) * 2);
                    ldsm4(uBh + bo, bh[0], bh[1], bh[2], bh[3]);
                    ldsm4(uBl + bo, bl[0], bl[1], bl[2], bl[3]);
                    #pragma unroll
                    for (int h = 0; h < 2; h++) {
                        const int nf = nf2 * 2 + h;
                        uint32_t* bhp = &bh[h * 2];
                        uint32_t* blp = &bl[h * 2];
                        #pragma unroll
                        for (int mf = 0; mf < 2; mf++) {
                            mma16816(acc[mf][nf], ah[mf], bhp);
                            mma16816(acc[mf][nf], ah[mf], blp);
                            mma16816(acc[mf][nf], al[mf], bhp);
                        }
                    }
                }
            }
        }
    }

    float* po = outp + (size_t)z * (size_t)sliceStride;
    #pragma unroll
    for (int mf = 0; mf < 2; mf++) {
        #pragma unroll
        for (int hh = 0; hh < 2; hh++) {
            const int m = m0 + wm * 32 + mf * 16 + (lane >> 2) + hh * 8;
            if (m >= Mrows) continue;
            const float sc = (mode == 1) ? aux2[m] : 0.f;
            #pragma unroll
            for (int nf = 0; nf < 8; nf++) {
                const int nb = n0 + wn * 64 + nf * 8 + (lane & 3) * 2;
                #pragma unroll
                for (int j = 0; j < 2; j++) {
                    const int n = nb + j;
                    if (n >= Nrows) continue;
                    const float t = acc[mf][nf][hh * 2 + j];
                    size_t ix = (size_t)m * ldc + n;
                    if (mode == 1) {
                        float rr = aux[(size_t)m * ldaux + n] - t;
                        rr = fminf(fmaxf(rr, -1e-3f), 1e-3f);
                        po[ix] = sc * t + rr;
                    } else {
                        po[ix] = t;
                    }
                }
            }
        }
    }
}

// ---------------------------------------------------------------------------
// Persistent solve: power iteration + alpha + initX + Richardson(split-K 8,
// 128 CTAs) + clip scale. All in ONE launch.
// ---------------------------------------------------------------------------
__device__ __forceinline__ void gridbar(unsigned int k) {
    __syncthreads();
    if (threadIdx.x == 0) {
        unsigned int* bar = &g_bar;
        asm volatile("red.release.gpu.global.add.u32 [%0], 1;" :: "l"(bar) : "memory");
        unsigned int target = NCTA_SOLVE * k;
        unsigned int cur;
        do {
            asm volatile("ld.acquire.gpu.global.u32 %0, [%1];" : "=r"(cur) : "l"(bar) : "memory");
            if (cur >= target) break;
            __nanosleep(64);
        } while (true);
    }
    __syncthreads();
}

__global__ void __launch_bounds__(256, 2) solve_k()
{
    extern __shared__ __align__(16) char smem[];
    const uint32_t sbase = smem_u32(smem);
    const int bx = blockIdx.x;           // 0..127
    const int tid = threadIdx.x, lane = tid & 31, wid = tid >> 5;
    const int wm = wid >> 1, wn = wid & 1;
    unsigned int nb = 0;

    // ---- power iteration (ping-pong v/y, fixed 1e-5 rescale) ----
    {
        int j = bx * 2 + (tid >> 7);     // 2 elems per CTA x 128 CTAs = 256... need 1000
    }
    // v0 = 1e-5 * S row 0 ; distribute j over first 4 CTAs' threads
    for (int j = bx * 256 + tid; j < NA; j += NCTA_SOLVE * 256)
        g_v[j] = g_S[j] * 1e-5f;
    gridbar(++nb);

    float* vcur = g_v;
    float* vnxt = g_y;
    for (int p = 0; p < POW_ITERS; p++) {
        const int r = bx * 8 + wid;      // 1024 warps cover 1000 rows
        if (r < NA) {
            float s = 0.f;
            for (int j = lane; j < NA; j += 32)
                s += g_S[r * NA + j] * __ldcg(&vcur[j]);
            #pragma unroll
            for (int o = 16; o > 0; o >>= 1)
                s += __shfl_down_sync(0xffffffffu, s, o);
            if (lane == 0) vnxt[r] = s * 1e-5f;
        }
        gridbar(++nb);
        float* t = vcur; vcur = vnxt; vnxt = t;
    }
    // lambda = 1e5 * ||vcur|| / ||vnxt||  (vnxt holds previous iterate)
    // computed redundantly per CTA (deterministic, identical across CTAs)
    float alpha;
    {
        __shared__ float sh[256];
        float s1 = 0.f, s0 = 0.f;
        for (int j = tid; j < NA; j += 256) {
            float a = __ldcg(&vcur[j]);
            float b = __ldcg(&vnxt[j]);
            s1 += a * a; s0 += b * b;
        }
        sh[tid] = s1; __syncthreads();
        for (int o = 128; o > 0; o >>= 1) {
            if (tid < o) sh[tid] += sh[tid + o];
            __syncthreads();
        }
        s1 = sh[0]; __syncthreads();
        sh[tid] = s0; __syncthreads();
        for (int o = 128; o > 0; o >>= 1) {
            if (tid < o) sh[tid] += sh[tid + o];
            __syncthreads();
        }
        s0 = sh[0]; __syncthreads();
        const float lam = 1e5f * sqrtf(s1 / s0);
        alpha = 1.2f / lam;
    }

    // ---- initX: X = alpha*C, split into ping buffer 0 (CTA-private slice) ----
    const int sl0 = bx * 2048;
    for (int i = tid; i < 2048; i += 256) {
        const int idx = sl0 + i;
        const int m = idx >> 10, n = idx & 1023;
        if (n < NA) {
            float v = alpha * g_Cm[m * NA + n];
            g_X[m * NA + n] = v;
            __nv_bfloat16 h = __float2bfloat16(v);
            g_XH0[idx] = h;
            g_XL0[idx] = __float2bfloat16(v - __bfloat162float(h));
        }
    }
    gridbar(++nb);

    // ---- Richardson: split-K 8 across 128 CTAs ----
    const int z  = bx & 7;
    const int tl = bx >> 3;              // 0..15
    const int m0 = (tl >> 3) * 128;
    const int n0 = (tl & 7) * 128;
    const int kb0 = z * 128;

    for (int t = 0; t < RICH_ITERS; t++) {
        const __nv_bfloat16* inH = (t & 1) ? g_XH1 : g_XH0;
        const __nv_bfloat16* inL = (t & 1) ? g_XL1 : g_XL0;
        __nv_bfloat16* outH = (t & 1) ? g_XH0 : g_XH1;
        __nv_bfloat16* outL = (t & 1) ? g_XL0 : g_XL1;

        float acc[2][8][4];
        #pragma unroll
        for (int i = 0; i < 2; i++)
            #pragma unroll
            for (int j = 0; j < 8; j++)
                #pragma unroll
                for (int q = 0; q < 4; q++) acc[i][j][q] = 0.f;

        gemm_mainloop<true>(inH, inL, KPAD, BD, m0, g_SH, g_SL, KPAD, NA, n0,
                            kb0, 4, sbase, acc, true);

        // write partial tile into g_Rp[z]
        float* rp = g_Rp[z];
        #pragma unroll
        for (int mf = 0; mf < 2; mf++) {
            #pragma unroll
            for (int hh = 0; hh < 2; hh++) {
                const int m = m0 + wm * 32 + mf * 16 + (lane >> 2) + hh * 8;
                #pragma unroll
                for (int nf = 0; nf < 8; nf++) {
                    const int nbase = n0 + wn * 64 + nf * 8 + (lane & 3) * 2;
                    #pragma unroll
                    for (int j = 0; j < 2; j++)
                        rp[m * KPAD + nbase + j] = acc[mf][nf][hh * 2 + j];
                }
            }
        }
        gridbar(++nb);

        // reduce partials + update X + re-split (CTA-private slice)
        for (int i = tid; i < 2048; i += 256) {
            const int idx = sl0 + i;
            const int m = idx >> 10, n = idx & 1023;
            if (n < NA) {
                float tv = 0.f;
                #pragma unroll
                for (int zz = 0; zz < ZSOLVE; zz++)
                    tv += __ldcg(&g_Rp[zz][idx]);
                const int ix = m * NA + n;
                float xnew = g_X[ix] + alpha * (g_Cm[ix] - tv);
                g_X[ix] = xnew;
                __nv_bfloat16 h = __float2bfloat16(xnew);
                outH[idx] = h;
                outL[idx] = __float2bfloat16(xnew - __bfloat162float(h));
            }
        }
        gridbar(++nb);
    }

    // ---- clip scale: rows 2 per CTA ----
    if (wid < 2) {
        const int row = bx * 2 + wid;
        float d = 0.f;
        for (int j = lane; j < NA; j += 32)
            d += __ldcg(&g_X[row * NA + j]) * g_Cm[row * NA + j];
        #pragma unroll
        for (int o = 16; o > 0; o >>= 1)
            d += __shfl_down_sync(0xffffffffu, d, o);
        if (lane == 0)
            g_scale[row] = fminf(rsqrtf(fmaxf(d, 1e-30f)), 1.0f);
    }
}

// ---------------- small kernels ----------------
__global__ void split_k(const float* __restrict__ s, __nv_bfloat16* __restrict__ h,
                        __nv_bfloat16* __restrict__ l, size_t n4) {
    size_t i = (size_t)blockIdx.x * blockDim.x + threadIdx.x;
    if (i < n4) {
        float4 v = ((const float4*)s)[i];
        float vv[4] = {v.x, v.y, v.z, v.w};
        #pragma unroll
        for (int j = 0; j < 4; j++) {
            __nv_bfloat16 hh = __float2bfloat16(vv[j]);
            h[i * 4 + j] = hh;
            l[i * 4 + j] = __float2bfloat16(vv[j] - __bfloat162float(hh));
        }
    }
}
__global__ void zerobar_k() { g_bar = 0u; }

__global__ void reduceS_split_k() {
    int idx = blockIdx.x * blockDim.x + threadIdx.x;
    if (idx < NA * NA) {
        int i = idx / NA, j = idx % NA;
        if (i >= j) {
            float s = 0.f;
            #pragma unroll
            for (int zz = 0; zz < 8; zz++) s += g_Sp[zz][idx];
            g_S[i * NA + j] = s;
            g_S[j * NA + i] = s;
            __nv_bfloat16 h = __float2bfloat16(s);
            __nv_bfloat16 l = __float2bfloat16(s - __bfloat162float(h));
            g_SH[i * KPAD + j] = h; g_SL[i * KPAD + j] = l;
            g_SH[j * KPAD + i] = h; g_SL[j * KPAD + i] = l;
        }
    }
}
__global__ void reduceC_k() {
    int idx = blockIdx.x * blockDim.x + threadIdx.x;
    if (idx < BD * NA) {
        float s = 0.f;
        #pragma unroll
        for (int zz = 0; zz < 16; zz++) s += g_Cp[zz][idx];
        g_Cm[idx] = s;
    }
}

// ---------------------------------------------------------------------------
extern "C" void kernel_launch(void* const* d_in, const int* in_sizes, int n_in,
                              void* d_out, int out_size)
{
    const float* pub  = (const float*)d_in[0];
    const float* priv = (const float*)d_in[1];
    float* out = (float*)d_out;

    cudaFuncSetAttribute(gemm_tc<0>, cudaFuncAttributeMaxDynamicSharedMemorySize, 2 * STAGE_B);
    cudaFuncSetAttribute(gemm_tc<1>, cudaFuncAttributeMaxDynamicSharedMemorySize, 2 * STAGE_B);
    cudaFuncSetAttribute(solve_k, cudaFuncAttributeMaxDynamicSharedMemorySize, 2 * STAGE_B);

    __nv_bfloat16 *pubH, *pubL, *privH, *privL, *XH1, *XL1;
    float *Sp, *Cp, *scal;
    cudaGetSymbolAddress((void**)&pubH, g_pubH);
    cudaGetSymbolAddress((void**)&pubL, g_pubL);
    cudaGetSymbolAddress((void**)&privH, g_privH);
    cudaGetSymbolAddress((void**)&privL, g_privL);
    cudaGetSymbolAddress((void**)&XH1, g_XH1);
    cudaGetSymbolAddress((void**)&XL1, g_XL1);
    cudaGetSymbolAddress((void**)&Sp, g_Sp);
    cudaGetSymbolAddress((void**)&Cp, g_Cp);
    cudaGetSymbolAddress((void**)&scal, g_scale);

    // 1-2) splits; 3) barrier reset (launch #3)
    {
        size_t n4 = (size_t)NA * KP / 4;
        split_k<<<(unsigned)((n4 + 255) / 256), 256>>>(pub, pubH, pubL, n4);
        n4 = (size_t)BD * KP / 4;
        split_k<<<(unsigned)((n4 + 255) / 256), 256>>>(priv, privH, privL, n4);
    }
    zerobar_k<<<1, 1>>>();

    // 4) S = pub*pub^T — tri + 2-pass split, split-K 8 (profiled launch #4)
    gemm_tc<0><<<dim3(8, 8, 8), 256, 2 * STAGE_B>>>(
        pubH, pubL, KP, NA, pubH, pubL, nullptr, KP, NA,
        KP, 391, Sp, (long long)NA * NA, NA, 0, nullptr, 0, nullptr, 1);
    reduceS_split_k<<<(NA * NA + 255) / 256, 256>>>();

    // 5) C = priv*pub^T — full 3-pass, split-K 16 (256 CTAs)
    gemm_tc<0><<<dim3(8, 2, 16), 256, 2 * STAGE_B>>>(
        privH, privL, KP, BD, pubH, pubL, nullptr, KP, NA,
        KP, 196, Cp, (long long)BD * NA, NA, 0, nullptr, 0, nullptr, 0);
    reduceC_k<<<(BD * NA + 255) / 256, 256>>>();

    // 6) persistent solve: power iter + initX + 9 Richardson (128 CTAs) + scale
    solve_k<<<NCTA_SOLVE, 256, 2 * STAGE_B>>>();

    // 7) out = scale*T + clamp(priv - T, +-1e-3), T = X*pub (inline transpose)
    gemm_tc<1><<<dim3(782, 2, 1), 256, STAGE_B>>>(
        XH1, XL1, KPAD, BD, nullptr, nullptr, pub, KP, KP,
        KPAD, 32, out, 0, KP, 1, priv, KP, scal, 0);
}